// round 14
// baseline (speedup 1.0000x reference)
#include <cuda_runtime.h>
#include <cstdint>
#include <math.h>

#define B_ROWS   262144
#define STEPS    10
#define NTHREADS 256     // phase1
#define LTHREADS 128     // langevin: 4 warps, each owns 16 rows

__device__ double g_sum;
__device__ float  g_noise_scale;

// ---- phase1 SMEM layout ----
#define XT_ROW 164
#define XT_CLS 40
#define PL_ROW 132
#define P1_XT  0
#define P1_XST (64*XT_ROW)
#define P1_WORDS (P1_XST + 64*PL_ROW)
#define P1_SMEM (P1_WORDS*4)

// ---- langevin SMEM (words): J fragments + thread-private C ----
#define FRAG_OFF 0                  // 8*16*64 = 8192 words
#define C_OFF    8192               // 128 threads * 66 words
#define LG_WORDS (8192 + 128*66)    // 16640
#define LG_SMEM  (LG_WORDS*4)       // 66560 B -> 3 CTAs/SM

// ---------------------------------------------------------------------------
// MMA helpers
// ---------------------------------------------------------------------------
__device__ __forceinline__ uint32_t f2tf32(float f) {
    uint32_t r;
    asm("cvt.rna.tf32.f32 %0, %1;" : "=r"(r) : "f"(f));
    return r;
}
__device__ __forceinline__ void mma_tf32(float d[4], const uint32_t a[4],
                                         const uint32_t b[2]) {
    asm volatile(
        "mma.sync.aligned.m16n8k8.row.col.f32.tf32.tf32.f32 "
        "{%0,%1,%2,%3}, {%4,%5,%6,%7}, {%8,%9}, {%0,%1,%2,%3};\n"
        : "+f"(d[0]), "+f"(d[1]), "+f"(d[2]), "+f"(d[3])
        : "r"(a[0]), "r"(a[1]), "r"(a[2]), "r"(a[3]), "r"(b[0]), "r"(b[1]));
}
__device__ __forceinline__ void mma_bf16(float d[4], const uint32_t a[4],
                                         uint32_t b0, uint32_t b1) {
    asm volatile(
        "mma.sync.aligned.m16n8k16.row.col.f32.bf16.bf16.f32 "
        "{%0,%1,%2,%3}, {%4,%5,%6,%7}, {%8,%9}, {%0,%1,%2,%3};\n"
        : "+f"(d[0]), "+f"(d[1]), "+f"(d[2]), "+f"(d[3])
        : "r"(a[0]), "r"(a[1]), "r"(a[2]), "r"(a[3]), "r"(b0), "r"(b1));
}
__device__ __forceinline__ uint32_t pack_bf16(float hi, float lo) {
    uint32_t r;
    asm("cvt.rn.bf16x2.f32 %0, %1, %2;" : "=r"(r) : "f"(hi), "f"(lo));
    return r;
}
__device__ __forceinline__ float tanh_fast(float x) {
    float r;
    asm("tanh.approx.f32 %0, %1;" : "=f"(r) : "f"(x));
    return r;
}
__device__ __forceinline__ uint32_t imad1(uint32_t a, uint32_t one, uint32_t b) {
    uint32_t r;
    asm("mad.lo.u32 %0, %1, %2, %3;" : "=r"(r) : "r"(a), "r"(one), "r"(b));
    return r;
}

// ---------------------------------------------------------------------------
// Threefry-2x32/20
// ---------------------------------------------------------------------------
__host__ __forceinline__ void threefry_host(
    uint32_t k0, uint32_t k1, uint32_t x0, uint32_t x1,
    uint32_t& o0, uint32_t& o1)
{
    uint32_t ks0 = k0, ks1 = k1, ks2 = k0 ^ k1 ^ 0x1BD11BDAu;
    x0 += ks0; x1 += ks1;
#define TF_R(r) { x0 += x1; x1 = (x1 << (r)) | (x1 >> (32 - (r))); x1 ^= x0; }
    TF_R(13) TF_R(15) TF_R(26) TF_R(6)
    x0 += ks1; x1 += ks2 + 1u;
    TF_R(17) TF_R(29) TF_R(16) TF_R(24)
    x0 += ks2; x1 += ks0 + 2u;
    TF_R(13) TF_R(15) TF_R(26) TF_R(6)
    x0 += ks0; x1 += ks1 + 3u;
    TF_R(17) TF_R(29) TF_R(16) TF_R(24)
    x0 += ks1; x1 += ks2 + 4u;
    TF_R(13) TF_R(15) TF_R(26) TF_R(6)
    x0 += ks2; x1 += ks0 + 5u;
#undef TF_R
    o0 = x0; o1 = x1;
}

__device__ __forceinline__ uint32_t rnd_bits(uint32_t one,
    uint32_t k0, uint32_t k1, uint32_t idx)
{
    uint32_t ks2 = k0 ^ k1 ^ 0x1BD11BDAu;
    uint32_t x0 = k0;
    uint32_t x1 = idx + k1;
#define TF_B(r) { x0 = imad1(x0, one, x1); x1 = __funnelshift_l(x1, x1, r); x1 ^= x0; }
    TF_B(13) TF_B(15) TF_B(26) TF_B(6)
    x0 = imad1(x0, one, k1);  x1 += ks2 + 1u;
    TF_B(17) TF_B(29) TF_B(16) TF_B(24)
    x0 = imad1(x0, one, ks2); x1 += k0 + 2u;
    TF_B(13) TF_B(15) TF_B(26) TF_B(6)
    x0 = imad1(x0, one, k0);  x1 += k1 + 3u;
    TF_B(17) TF_B(29) TF_B(16) TF_B(24)
    x0 = imad1(x0, one, k1);  x1 += ks2 + 4u;
    TF_B(13) TF_B(15) TF_B(26) TF_B(6)
    x0 = imad1(x0, one, ks2); x1 += k0 + 5u;
#undef TF_B
    return x0 ^ x1;
}

__device__ __forceinline__ float bits_to_normal(uint32_t bits)
{
    const float lo = -0.99999994f;
    float u = __uint_as_float((bits >> 9) | 0x3f800000u) - 1.0f;
    float x = fmaf(u, 2.0f, lo);
    x = fmaxf(x, lo);
    float w = -__logf(fmaf(-x, x, 1.0f));
    float p;
    if (w < 5.0f) {
        w -= 2.5f;
        p = 2.81022636e-08f;
        p = fmaf(p, w, 3.43273939e-07f);
        p = fmaf(p, w, -3.5233877e-06f);
        p = fmaf(p, w, -4.39150654e-06f);
        p = fmaf(p, w, 0.00021858087f);
        p = fmaf(p, w, -0.00125372503f);
        p = fmaf(p, w, -0.00417768164f);
        p = fmaf(p, w, 0.246640727f);
        p = fmaf(p, w, 1.50140941f);
    } else {
        w = sqrtf(w) - 3.0f;
        p = -0.000200214257f;
        p = fmaf(p, w, 0.000100950558f);
        p = fmaf(p, w, 0.00134934322f);
        p = fmaf(p, w, -0.00367342844f);
        p = fmaf(p, w, 0.00573950773f);
        p = fmaf(p, w, -0.0076224613f);
        p = fmaf(p, w, 0.00943887047f);
        p = fmaf(p, w, 1.00167406f);
        p = fmaf(p, w, 2.83297682f);
    }
    return 1.41421354f * (p * x);
}

struct Keys { uint32_t k0[STEPS]; uint32_t k1[STEPS]; uint32_t one; };

__global__ void zero_kernel() { g_sum = 0.0; }
__global__ void finalize_kernel()
{
    double mean = g_sum * (1.0 / 33554432.0);
    float temp = 0.1f * (1.0f + (float)mean * 10.0f);
    g_noise_scale = sqrtf(2.0f * 0.1f * temp);
}

// ===========================================================================
// Phase 1 (unchanged — verified rounds 9-13)
// ===========================================================================
__global__ void __launch_bounds__(NTHREADS, 2) phase1_mma(
    const float* __restrict__ x_input, const float* __restrict__ W)
{
    extern __shared__ float sm[];
    uint32_t* smu = (uint32_t*)sm;
    int tid = threadIdx.x, w = tid >> 5, lane = tid & 31;
    int g = lane >> 2, i = lane & 3;
    int N0 = 16 * w;
    int tb = blockIdx.x * 64;

    const float4* W4 = (const float4*)W;
    for (int idx = tid; idx < 4096; idx += NTHREADS) {
        int r = idx >> 5, q = idx & 31;
        *(float4*)&sm[r * PL_ROW + 4 * q] = W4[idx];
    }
    __syncthreads();

    uint32_t Bf[16][2][2];
#pragma unroll
    for (int kk = 0; kk < 16; kk++)
#pragma unroll
        for (int j = 0; j < 2; j++) {
            Bf[kk][j][0] = f2tf32(sm[(8 * kk + i) * PL_ROW + N0 + 8 * j + g]);
            Bf[kk][j][1] = f2tf32(sm[(8 * kk + i + 4) * PL_ROW + N0 + 8 * j + g]);
        }
    __syncthreads();

    const float4* X4 = (const float4*)(x_input + (size_t)tb * 128);
    for (int idx = tid; idx < 2048; idx += NTHREADS) {
        int r = idx >> 5, q = idx & 31;
        float4 v = X4[idx];
        *(float4*)&sm[P1_XST + r * PL_ROW + 4 * q] = v;
        smu[P1_XT + r * XT_ROW + 0 * XT_CLS + q] = f2tf32(v.x);
        smu[P1_XT + r * XT_ROW + 1 * XT_CLS + q] = f2tf32(v.y);
        smu[P1_XT + r * XT_ROW + 2 * XT_CLS + q] = f2tf32(v.z);
        smu[P1_XT + r * XT_ROW + 3 * XT_CLS + q] = f2tf32(v.w);
    }
    __syncthreads();

    int cA = N0 + 2 * i, cB = cA + 8;
    float acc = 0.f;
#pragma unroll 1
    for (int R = 0; R < 4; R++) {
        int r0 = 16 * R + g, r1 = r0 + 8;
        float D0[4] = {0,0,0,0}, D1[4] = {0,0,0,0};
        const uint32_t* xt0 = &smu[P1_XT + r0 * XT_ROW + i * XT_CLS];
        const uint32_t* xt1 = &smu[P1_XT + r1 * XT_ROW + i * XT_CLS];
#pragma unroll
        for (int j = 0; j < 8; j++) {
            uint4 va = *(const uint4*)(xt0 + 4 * j);
            uint4 vb = *(const uint4*)(xt1 + 4 * j);
            uint32_t a[4];
            a[0] = va.x; a[1] = vb.x; a[2] = va.y; a[3] = vb.y;
            mma_tf32(D0, a, Bf[2 * j][0]);
            mma_tf32(D1, a, Bf[2 * j][1]);
            a[0] = va.z; a[1] = vb.z; a[2] = va.w; a[3] = vb.w;
            mma_tf32(D0, a, Bf[2 * j + 1][0]);
            mma_tf32(D1, a, Bf[2 * j + 1][1]);
        }
        float2 x00 = *(float2*)&sm[P1_XST + r0 * PL_ROW + cA];
        float2 x01 = *(float2*)&sm[P1_XST + r0 * PL_ROW + cB];
        float2 x10 = *(float2*)&sm[P1_XST + r1 * PL_ROW + cA];
        float2 x11 = *(float2*)&sm[P1_XST + r1 * PL_ROW + cB];
        float e;
        e = x00.x - tanh_fast(D0[0]); acc = fmaf(e, e, acc);
        e = x00.y - tanh_fast(D0[1]); acc = fmaf(e, e, acc);
        e = x01.x - tanh_fast(D1[0]); acc = fmaf(e, e, acc);
        e = x01.y - tanh_fast(D1[1]); acc = fmaf(e, e, acc);
        e = x10.x - tanh_fast(D0[2]); acc = fmaf(e, e, acc);
        e = x10.y - tanh_fast(D0[3]); acc = fmaf(e, e, acc);
        e = x11.x - tanh_fast(D1[2]); acc = fmaf(e, e, acc);
        e = x11.y - tanh_fast(D1[3]); acc = fmaf(e, e, acc);
    }
    double da = (double)acc;
#pragma unroll
    for (int off = 16; off; off >>= 1)
        da += __shfl_xor_sync(0xffffffffu, da, off);
    __shared__ double sacc[8];
    if (lane == 0) sacc[w] = da;
    __syncthreads();
    if (tid == 0) {
        double t = 0.0;
#pragma unroll
        for (int k = 0; k < 8; k++) t += sacc[k];
        atomicAdd(&g_sum, t);
    }
}

// ===========================================================================
// Langevin, warp-private: warp owns 16 rows; x state in registers laid out
// as m16n8k16 A-fragments; D-fragment ownership == A-slot ownership, so the
// MMA is the ONLY cross-thread exchange. One __syncthreads total.
//   Thread (g=lane>>2, i=lane&3) owns, per k-block kk (0..7):
//   slots: [0]=(row g,   col 16kk+2i)   [1]=(g,   +1)
//          [2]=(row g+8, col 16kk+2i)   [3]=(g+8, +1)
//          [4]=(g,  col 16kk+2i+8)      [5]=(g,  +9)
//          [6]=(g+8,col 16kk+2i+8)      [7]=(g+8,+9)
// ===========================================================================
__global__ void __launch_bounds__(LTHREADS, 3) langevin_wp(
    const float* __restrict__ x_input, const float* __restrict__ J,
    const float* __restrict__ h, float* __restrict__ out, Keys keys)
{
    extern __shared__ float sm[];
    uint32_t* fragS = (uint32_t*)sm;        // [kk*16+nt][lane*2 + q]
    float* Cs = sm + C_OFF;                 // thread-private, stride 66
    int tid = threadIdx.x, w = tid >> 5, lane = tid & 31;
    int g = lane >> 2, i = lane & 3;
    int tb = blockIdx.x * 64;
    int r0g = tb + 16 * w + g, r1g = r0g + 8;
    uint32_t one = keys.one;

    // ---- B-fragment prep: pair p = (kk,nt); each lane writes its 2 words ----
#pragma unroll
    for (int t = 0; t < 32; t++) {
        int p = w * 32 + t;
        int kk = p >> 4, nt = p & 15;
        const float* Jb = J + (16 * kk + 2 * i) * 128 + 8 * nt + g;
        float j0 = Jb[0], j1 = Jb[128], j2 = Jb[8 * 128], j3 = Jb[9 * 128];
        fragS[p * 64 + lane * 2 + 0] = pack_bf16(j1, j0);
        fragS[p * 64 + lane * 2 + 1] = pack_bf16(j3, j2);
    }
    // ---- C = 0.1*(x_input - h), thread-private slots ----
#pragma unroll
    for (int kk = 0; kk < 8; kk++) {
        int c0 = 16 * kk + 2 * i, c2 = c0 + 8;
        float2 h0 = *(const float2*)(h + c0);
        float2 h2 = *(const float2*)(h + c2);
        float2 x00 = *(const float2*)(x_input + (size_t)r0g * 128 + c0);
        float2 x10 = *(const float2*)(x_input + (size_t)r1g * 128 + c0);
        float2 x02 = *(const float2*)(x_input + (size_t)r0g * 128 + c2);
        float2 x12 = *(const float2*)(x_input + (size_t)r1g * 128 + c2);
        float* cb = Cs + tid * 66 + kk * 8;
        cb[0] = 0.1f * (x00.x - h0.x); cb[1] = 0.1f * (x00.y - h0.y);
        cb[2] = 0.1f * (x10.x - h0.x); cb[3] = 0.1f * (x10.y - h0.y);
        cb[4] = 0.1f * (x02.x - h2.x); cb[5] = 0.1f * (x02.y - h2.y);
        cb[6] = 0.1f * (x12.x - h2.x); cb[7] = 0.1f * (x12.y - h2.y);
    }
    __syncthreads();            // the ONLY barrier
    float ns = g_noise_scale;

    float x[8][8];
#pragma unroll
    for (int kk = 0; kk < 8; kk++)
#pragma unroll
        for (int q = 0; q < 8; q++) x[kk][q] = 0.f;

    uint32_t A[8][4];

#pragma unroll 1
    for (int s = 0; s < STEPS; s++) {
        uint32_t kk0 = keys.k0[s], kk1 = keys.k1[s];
        // pack A from previous x (zeros at s=0 -> MMA yields exact 0)
#pragma unroll
        for (int kk = 0; kk < 8; kk++) {
            A[kk][0] = pack_bf16(x[kk][1], x[kk][0]);
            A[kk][1] = pack_bf16(x[kk][3], x[kk][2]);
            A[kk][2] = pack_bf16(x[kk][5], x[kk][4]);
            A[kk][3] = pack_bf16(x[kk][7], x[kk][6]);
        }
#pragma unroll
        for (int nt = 0; nt < 16; nt++) {
            float D[4] = {0.f, 0.f, 0.f, 0.f};
#pragma unroll
            for (int kk = 0; kk < 8; kk++) {
                uint2 b = *(const uint2*)&fragS[(kk * 16 + nt) * 64 + lane * 2];
                mma_bf16(D, A[kk], b.x, b.y);
            }
            const int ek = nt >> 1, eb = (nt & 1) * 4;
            int cb2 = 8 * nt + 2 * i;
            const float* cp = Cs + tid * 66 + ek * 8 + eb;
            float2 cc0 = *(const float2*)(cp);       // (row g) pair
            float2 cc1 = *(const float2*)(cp + 2);   // (row g+8) pair
            uint32_t i00 = (uint32_t)r0g * 128u + (uint32_t)cb2;
            uint32_t i10 = (uint32_t)r1g * 128u + (uint32_t)cb2;
            float n00 = bits_to_normal(rnd_bits(one, kk0, kk1, i00));
            float n01 = bits_to_normal(rnd_bits(one, kk0, kk1, i00 + 1u));
            float n10 = bits_to_normal(rnd_bits(one, kk0, kk1, i10));
            float n11 = bits_to_normal(rnd_bits(one, kk0, kk1, i10 + 1u));
            x[ek][eb + 0] = tanh_fast(fmaf(n00, ns, fmaf(D[0], -0.1f, x[ek][eb + 0] + cc0.x)));
            x[ek][eb + 1] = tanh_fast(fmaf(n01, ns, fmaf(D[1], -0.1f, x[ek][eb + 1] + cc0.y)));
            x[ek][eb + 2] = tanh_fast(fmaf(n10, ns, fmaf(D[2], -0.1f, x[ek][eb + 2] + cc1.x)));
            x[ek][eb + 3] = tanh_fast(fmaf(n11, ns, fmaf(D[3], -0.1f, x[ek][eb + 3] + cc1.y)));
        }
    }

    // ---- epilogue: registers -> gmem (8B-contiguous per 4-lane group) ----
#pragma unroll
    for (int kk = 0; kk < 8; kk++) {
        int c0 = 16 * kk + 2 * i, c2 = c0 + 8;
        *(float2*)(out + (size_t)r0g * 128 + c0) = make_float2(x[kk][0], x[kk][1]);
        *(float2*)(out + (size_t)r1g * 128 + c0) = make_float2(x[kk][2], x[kk][3]);
        *(float2*)(out + (size_t)r0g * 128 + c2) = make_float2(x[kk][4], x[kk][5]);
        *(float2*)(out + (size_t)r1g * 128 + c2) = make_float2(x[kk][6], x[kk][7]);
    }
}

// ===========================================================================
// Launch
// ===========================================================================
extern "C" void kernel_launch(void* const* d_in, const int* in_sizes, int n_in,
                              void* d_out, int out_size)
{
    const float* x_input = (const float*)d_in[0];
    const float* W       = (const float*)d_in[1];
    const float* J       = (const float*)d_in[2];
    const float* h       = (const float*)d_in[3];
    float* out           = (float*)d_out;

    Keys keys;
    for (int s = 0; s < STEPS; s++) {
        uint32_t o0, o1;
        threefry_host(0u, 1u, 0u, (uint32_t)s, o0, o1);
        keys.k0[s] = o0;
        keys.k1[s] = o1;
    }
    keys.one = 1u;

    static bool attr_set = false;
    if (!attr_set) {
        cudaFuncSetAttribute(phase1_mma,
            cudaFuncAttributeMaxDynamicSharedMemorySize, P1_SMEM);
        cudaFuncSetAttribute(langevin_wp,
            cudaFuncAttributeMaxDynamicSharedMemorySize, LG_SMEM);
        attr_set = true;
    }

    const int NT = B_ROWS / 64;   // 4096
    zero_kernel<<<1, 1>>>();
    phase1_mma<<<NT, NTHREADS, P1_SMEM>>>(x_input, W);
    finalize_kernel<<<1, 1>>>();
    langevin_wp<<<NT, LTHREADS, LG_SMEM>>>(x_input, J, h, out, keys);
}

// round 15
// speedup vs baseline: 1.2616x; 1.2616x over previous
#include <cuda_runtime.h>
#include <cstdint>
#include <math.h>

#define B_ROWS   262144
#define STEPS    10
#define NTHREADS 256

__device__ double g_sum;
__device__ float  g_noise_scale;

// ---- phase1 SMEM layout ----
#define XT_ROW 164
#define XT_CLS 40
#define PL_ROW 132
#define P1_XT  0
#define P1_XST (64*XT_ROW)
#define P1_WORDS (P1_XST + 64*PL_ROW)
#define P1_SMEM (P1_WORDS*4)

// ---- langevin SMEM layout (words) — round-10 verified ----
#define CSP  20
#define ROWP 80
#define XTB  (64*ROWP)
#define LG_XT0 0
#define LG_XT1 XTB
#define LG_SH  (2*XTB)
#define LG_XEX LG_SH
#define LG_C   (LG_SH + 64*PL_ROW)
#define LG_WORDS (LG_SH + 16896)
#define LG_SMEM (LG_WORDS*4)    // 108544 B -> 2 CTAs/SM

// ---------------------------------------------------------------------------
// MMA helpers
// ---------------------------------------------------------------------------
__device__ __forceinline__ uint32_t f2tf32(float f) {
    uint32_t r;
    asm("cvt.rna.tf32.f32 %0, %1;" : "=r"(r) : "f"(f));
    return r;
}
__device__ __forceinline__ void mma_tf32(float d[4], const uint32_t a[4],
                                         const uint32_t b[2]) {
    asm volatile(
        "mma.sync.aligned.m16n8k8.row.col.f32.tf32.tf32.f32 "
        "{%0,%1,%2,%3}, {%4,%5,%6,%7}, {%8,%9}, {%0,%1,%2,%3};\n"
        : "+f"(d[0]), "+f"(d[1]), "+f"(d[2]), "+f"(d[3])
        : "r"(a[0]), "r"(a[1]), "r"(a[2]), "r"(a[3]), "r"(b[0]), "r"(b[1]));
}
__device__ __forceinline__ void mma_bf16(float d[4], const uint32_t a[4],
                                         const uint32_t b[2]) {
    asm volatile(
        "mma.sync.aligned.m16n8k16.row.col.f32.bf16.bf16.f32 "
        "{%0,%1,%2,%3}, {%4,%5,%6,%7}, {%8,%9}, {%0,%1,%2,%3};\n"
        : "+f"(d[0]), "+f"(d[1]), "+f"(d[2]), "+f"(d[3])
        : "r"(a[0]), "r"(a[1]), "r"(a[2]), "r"(a[3]), "r"(b[0]), "r"(b[1]));
}
__device__ __forceinline__ uint32_t pack_bf16(float hi, float lo) {
    uint32_t r;
    asm("cvt.rn.bf16x2.f32 %0, %1, %2;" : "=r"(r) : "f"(hi), "f"(lo));
    return r;
}
__device__ __forceinline__ float tanh_fast(float x) {
    float r;
    asm("tanh.approx.f32 %0, %1;" : "=f"(r) : "f"(x));
    return r;
}
__device__ __forceinline__ uint32_t imad1(uint32_t a, uint32_t one, uint32_t b) {
    uint32_t r;
    asm("mad.lo.u32 %0, %1, %2, %3;" : "=r"(r) : "r"(a), "r"(one), "r"(b));
    return r;
}

// ---------------------------------------------------------------------------
// Threefry-2x32/20
// ---------------------------------------------------------------------------
__host__ __forceinline__ void threefry_host(
    uint32_t k0, uint32_t k1, uint32_t x0, uint32_t x1,
    uint32_t& o0, uint32_t& o1)
{
    uint32_t ks0 = k0, ks1 = k1, ks2 = k0 ^ k1 ^ 0x1BD11BDAu;
    x0 += ks0; x1 += ks1;
#define TF_R(r) { x0 += x1; x1 = (x1 << (r)) | (x1 >> (32 - (r))); x1 ^= x0; }
    TF_R(13) TF_R(15) TF_R(26) TF_R(6)
    x0 += ks1; x1 += ks2 + 1u;
    TF_R(17) TF_R(29) TF_R(16) TF_R(24)
    x0 += ks2; x1 += ks0 + 2u;
    TF_R(13) TF_R(15) TF_R(26) TF_R(6)
    x0 += ks0; x1 += ks1 + 3u;
    TF_R(17) TF_R(29) TF_R(16) TF_R(24)
    x0 += ks1; x1 += ks2 + 4u;
    TF_R(13) TF_R(15) TF_R(26) TF_R(6)
    x0 += ks2; x1 += ks0 + 5u;
#undef TF_R
    o0 = x0; o1 = x1;
}

__device__ __forceinline__ uint32_t rnd_bits(uint32_t one,
    uint32_t k0, uint32_t k1, uint32_t idx)
{
    uint32_t ks2 = k0 ^ k1 ^ 0x1BD11BDAu;
    uint32_t x0 = k0;
    uint32_t x1 = idx + k1;
#define TF_B(r) { x0 = imad1(x0, one, x1); x1 = __funnelshift_l(x1, x1, r); x1 ^= x0; }
    TF_B(13) TF_B(15) TF_B(26) TF_B(6)
    x0 = imad1(x0, one, k1);  x1 += ks2 + 1u;
    TF_B(17) TF_B(29) TF_B(16) TF_B(24)
    x0 = imad1(x0, one, ks2); x1 += k0 + 2u;
    TF_B(13) TF_B(15) TF_B(26) TF_B(6)
    x0 = imad1(x0, one, k0);  x1 += k1 + 3u;
    TF_B(17) TF_B(29) TF_B(16) TF_B(24)
    x0 = imad1(x0, one, k1);  x1 += ks2 + 4u;
    TF_B(13) TF_B(15) TF_B(26) TF_B(6)
    x0 = imad1(x0, one, ks2); x1 += k0 + 5u;
#undef TF_B
    return x0 ^ x1;
}

__device__ __forceinline__ float bits_to_normal(uint32_t bits)
{
    const float lo = -0.99999994f;
    float u = __uint_as_float((bits >> 9) | 0x3f800000u) - 1.0f;
    float x = fmaf(u, 2.0f, lo);
    x = fmaxf(x, lo);
    float w = -__logf(fmaf(-x, x, 1.0f));
    float p;
    if (w < 5.0f) {
        w -= 2.5f;
        p = 2.81022636e-08f;
        p = fmaf(p, w, 3.43273939e-07f);
        p = fmaf(p, w, -3.5233877e-06f);
        p = fmaf(p, w, -4.39150654e-06f);
        p = fmaf(p, w, 0.00021858087f);
        p = fmaf(p, w, -0.00125372503f);
        p = fmaf(p, w, -0.00417768164f);
        p = fmaf(p, w, 0.246640727f);
        p = fmaf(p, w, 1.50140941f);
    } else {
        w = sqrtf(w) - 3.0f;
        p = -0.000200214257f;
        p = fmaf(p, w, 0.000100950558f);
        p = fmaf(p, w, 0.00134934322f);
        p = fmaf(p, w, -0.00367342844f);
        p = fmaf(p, w, 0.00573950773f);
        p = fmaf(p, w, -0.0076224613f);
        p = fmaf(p, w, 0.00943887047f);
        p = fmaf(p, w, 1.00167406f);
        p = fmaf(p, w, 2.83297682f);
    }
    return 1.41421354f * (p * x);
}

struct Keys { uint32_t k0[STEPS]; uint32_t k1[STEPS]; uint32_t one; };

__global__ void zero_kernel() { g_sum = 0.0; }
__global__ void finalize_kernel()
{
    double mean = g_sum * (1.0 / 33554432.0);
    float temp = 0.1f * (1.0f + (float)mean * 10.0f);
    g_noise_scale = sqrtf(2.0f * 0.1f * temp);
}

__device__ __forceinline__ float2 elw2(uint32_t one, float d0, float d1,
    float2 xo, float2 cc, uint32_t row_g, uint32_t col0,
    uint32_t kk0, uint32_t kk1, float nscale)
{
    uint32_t base = row_g * 128u + col0;
    float n0 = bits_to_normal(rnd_bits(one, kk0, kk1, base));
    float n1 = bits_to_normal(rnd_bits(one, kk0, kk1, base + 1u));
    float2 r;
    r.x = tanh_fast(fmaf(n0, nscale, fmaf(d0, -0.1f, xo.x + cc.x)));
    r.y = tanh_fast(fmaf(n1, nscale, fmaf(d1, -0.1f, xo.y + cc.y)));
    return r;
}

// ===========================================================================
// Phase 1 (unchanged — verified rounds 9-14)
// ===========================================================================
__global__ void __launch_bounds__(NTHREADS, 2) phase1_mma(
    const float* __restrict__ x_input, const float* __restrict__ W)
{
    extern __shared__ float sm[];
    uint32_t* smu = (uint32_t*)sm;
    int tid = threadIdx.x, w = tid >> 5, lane = tid & 31;
    int g = lane >> 2, i = lane & 3;
    int N0 = 16 * w;
    int tb = blockIdx.x * 64;

    const float4* W4 = (const float4*)W;
    for (int idx = tid; idx < 4096; idx += NTHREADS) {
        int r = idx >> 5, q = idx & 31;
        *(float4*)&sm[r * PL_ROW + 4 * q] = W4[idx];
    }
    __syncthreads();

    uint32_t Bf[16][2][2];
#pragma unroll
    for (int kk = 0; kk < 16; kk++)
#pragma unroll
        for (int j = 0; j < 2; j++) {
            Bf[kk][j][0] = f2tf32(sm[(8 * kk + i) * PL_ROW + N0 + 8 * j + g]);
            Bf[kk][j][1] = f2tf32(sm[(8 * kk + i + 4) * PL_ROW + N0 + 8 * j + g]);
        }
    __syncthreads();

    const float4* X4 = (const float4*)(x_input + (size_t)tb * 128);
    for (int idx = tid; idx < 2048; idx += NTHREADS) {
        int r = idx >> 5, q = idx & 31;
        float4 v = X4[idx];
        *(float4*)&sm[P1_XST + r * PL_ROW + 4 * q] = v;
        smu[P1_XT + r * XT_ROW + 0 * XT_CLS + q] = f2tf32(v.x);
        smu[P1_XT + r * XT_ROW + 1 * XT_CLS + q] = f2tf32(v.y);
        smu[P1_XT + r * XT_ROW + 2 * XT_CLS + q] = f2tf32(v.z);
        smu[P1_XT + r * XT_ROW + 3 * XT_CLS + q] = f2tf32(v.w);
    }
    __syncthreads();

    int cA = N0 + 2 * i, cB = cA + 8;
    float acc = 0.f;
#pragma unroll 1
    for (int R = 0; R < 4; R++) {
        int r0 = 16 * R + g, r1 = r0 + 8;
        float D0[4] = {0,0,0,0}, D1[4] = {0,0,0,0};
        const uint32_t* xt0 = &smu[P1_XT + r0 * XT_ROW + i * XT_CLS];
        const uint32_t* xt1 = &smu[P1_XT + r1 * XT_ROW + i * XT_CLS];
#pragma unroll
        for (int j = 0; j < 8; j++) {
            uint4 va = *(const uint4*)(xt0 + 4 * j);
            uint4 vb = *(const uint4*)(xt1 + 4 * j);
            uint32_t a[4];
            a[0] = va.x; a[1] = vb.x; a[2] = va.y; a[3] = vb.y;
            mma_tf32(D0, a, Bf[2 * j][0]);
            mma_tf32(D1, a, Bf[2 * j][1]);
            a[0] = va.z; a[1] = vb.z; a[2] = va.w; a[3] = vb.w;
            mma_tf32(D0, a, Bf[2 * j + 1][0]);
            mma_tf32(D1, a, Bf[2 * j + 1][1]);
        }
        float2 x00 = *(float2*)&sm[P1_XST + r0 * PL_ROW + cA];
        float2 x01 = *(float2*)&sm[P1_XST + r0 * PL_ROW + cB];
        float2 x10 = *(float2*)&sm[P1_XST + r1 * PL_ROW + cA];
        float2 x11 = *(float2*)&sm[P1_XST + r1 * PL_ROW + cB];
        float e;
        e = x00.x - tanh_fast(D0[0]); acc = fmaf(e, e, acc);
        e = x00.y - tanh_fast(D0[1]); acc = fmaf(e, e, acc);
        e = x01.x - tanh_fast(D1[0]); acc = fmaf(e, e, acc);
        e = x01.y - tanh_fast(D1[1]); acc = fmaf(e, e, acc);
        e = x10.x - tanh_fast(D0[2]); acc = fmaf(e, e, acc);
        e = x10.y - tanh_fast(D0[3]); acc = fmaf(e, e, acc);
        e = x11.x - tanh_fast(D1[2]); acc = fmaf(e, e, acc);
        e = x11.y - tanh_fast(D1[3]); acc = fmaf(e, e, acc);
    }
    double da = (double)acc;
#pragma unroll
    for (int off = 16; off; off >>= 1)
        da += __shfl_xor_sync(0xffffffffu, da, off);
    __shared__ double sacc[8];
    if (lane == 0) sacc[w] = da;
    __syncthreads();
    if (tid == 0) {
        double t = 0.0;
#pragma unroll
        for (int k = 0; k < 8; k++) t += sacc[k];
        atomicAdd(&g_sum, t);
    }
}

// ===========================================================================
// Langevin (round-10 base + warp-staggered chunks, noise-before-MMA,
// split accumulator chains). Double-buffered XT, 1 barrier/step, 2 CTAs/SM.
// ===========================================================================
__global__ void __launch_bounds__(NTHREADS, 2) langevin_bf16(
    const float* __restrict__ x_input, const float* __restrict__ J,
    const float* __restrict__ h, float* __restrict__ out, Keys keys)
{
    extern __shared__ float sm[];
    uint32_t* smu = (uint32_t*)sm;
    int tid = threadIdx.x, w = tid >> 5, lane = tid & 31;
    int g = lane >> 2, i = lane & 3;
    int N0 = 16 * w;
    int tb = blockIdx.x * 64;
    uint32_t one = keys.one;

    // stage J [128x128] (row stride 132) over XT/XEX union (dead until step 0)
    const float4* J4 = (const float4*)J;
    for (int idx = tid; idx < 4096; idx += NTHREADS) {
        int r = idx >> 5, q = idx & 31;
        *(float4*)&sm[r * PL_ROW + 4 * q] = J4[idx];
    }
    __syncthreads();

    uint32_t Bf[8][2][2];
#pragma unroll
    for (int kk = 0; kk < 8; kk++)
#pragma unroll
        for (int j = 0; j < 2; j++) {
            int c = N0 + 8 * j + g;
            int k0r = 16 * kk + 2 * i;
            float j0 = sm[(k0r    ) * PL_ROW + c];
            float j1 = sm[(k0r + 1) * PL_ROW + c];
            float j2 = sm[(k0r + 8) * PL_ROW + c];
            float j3 = sm[(k0r + 9) * PL_ROW + c];
            Bf[kk][j][0] = pack_bf16(j1, j0);
            Bf[kk][j][1] = pack_bf16(j3, j2);
        }
    __syncthreads();

    // C = 0.1*(xin - h)
    const float4* X4 = (const float4*)(x_input + (size_t)tb * 128);
    const float4* H4 = (const float4*)h;
    for (int idx = tid; idx < 2048; idx += NTHREADS) {
        int r = idx >> 5, q = idx & 31;
        float4 v = X4[idx], hv = H4[q];
        float4 c;
        c.x = 0.1f * (v.x - hv.x);
        c.y = 0.1f * (v.y - hv.y);
        c.z = 0.1f * (v.z - hv.z);
        c.w = 0.1f * (v.w - hv.w);
        *(float4*)&sm[LG_C + r * PL_ROW + 4 * q] = c;
    }
    float nscale = g_noise_scale;
    __syncthreads();

    int cA = N0 + 2 * i, cB = cA + 8;
    int sA = 2 * w, sB = 2 * w + 1;
    int xbase = CSP * i;

    // ---- step 0 ----
    {
        uint32_t kk0 = keys.k0[0], kk1 = keys.k1[0];
        float2 z = make_float2(0.f, 0.f);
#pragma unroll
        for (int Rr = 0; Rr < 4; Rr++) {
            int R = (Rr + w) & 3;
            int r0 = 16 * R + g, r1 = r0 + 8;
            float2 c00 = *(float2*)&sm[LG_C + r0 * PL_ROW + cA];
            float2 c01 = *(float2*)&sm[LG_C + r0 * PL_ROW + cB];
            float2 c10 = *(float2*)&sm[LG_C + r1 * PL_ROW + cA];
            float2 c11 = *(float2*)&sm[LG_C + r1 * PL_ROW + cB];
            float2 n00 = elw2(one, 0.f, 0.f, z, c00, tb + r0, cA, kk0, kk1, nscale);
            float2 n01 = elw2(one, 0.f, 0.f, z, c01, tb + r0, cB, kk0, kk1, nscale);
            float2 n10 = elw2(one, 0.f, 0.f, z, c10, tb + r1, cA, kk0, kk1, nscale);
            float2 n11 = elw2(one, 0.f, 0.f, z, c11, tb + r1, cB, kk0, kk1, nscale);
            *(float2*)&sm[LG_XEX + r0 * PL_ROW + cA] = n00;
            *(float2*)&sm[LG_XEX + r0 * PL_ROW + cB] = n01;
            *(float2*)&sm[LG_XEX + r1 * PL_ROW + cA] = n10;
            *(float2*)&sm[LG_XEX + r1 * PL_ROW + cB] = n11;
            smu[LG_XT0 + r0 * ROWP + xbase + sA] = pack_bf16(n00.y, n00.x);
            smu[LG_XT0 + r0 * ROWP + xbase + sB] = pack_bf16(n01.y, n01.x);
            smu[LG_XT0 + r1 * ROWP + xbase + sA] = pack_bf16(n10.y, n10.x);
            smu[LG_XT0 + r1 * ROWP + xbase + sB] = pack_bf16(n11.y, n11.x);
        }
    }
    __syncthreads();

    // ---- steps 1..9: 1 barrier/step; staggered chunks; noise before MMA ----
#pragma unroll 1
    for (int s = 1; s < STEPS; s++) {
        uint32_t kk0 = keys.k0[s], kk1 = keys.k1[s];
        bool lastS = (s == STEPS - 1);
        int xtR = ((s - 1) & 1) ? LG_XT1 : LG_XT0;
        int xtW = (s & 1) ? LG_XT1 : LG_XT0;
#pragma unroll
        for (int Rr = 0; Rr < 4; Rr++) {
            int R = (Rr + w) & 3;
            int r0 = 16 * R + g, r1 = r0 + 8;
            // --- noise first: 8 independent threefry chains (covers LDS/MMA) ---
            uint32_t i00 = (uint32_t)(tb + r0) * 128u + (uint32_t)cA;
            uint32_t i01 = (uint32_t)(tb + r0) * 128u + (uint32_t)cB;
            uint32_t i10 = (uint32_t)(tb + r1) * 128u + (uint32_t)cA;
            uint32_t i11 = (uint32_t)(tb + r1) * 128u + (uint32_t)cB;
            float nA0 = bits_to_normal(rnd_bits(one, kk0, kk1, i00));
            float nA1 = bits_to_normal(rnd_bits(one, kk0, kk1, i00 + 1u));
            float nB0 = bits_to_normal(rnd_bits(one, kk0, kk1, i01));
            float nB1 = bits_to_normal(rnd_bits(one, kk0, kk1, i01 + 1u));
            float nC0 = bits_to_normal(rnd_bits(one, kk0, kk1, i10));
            float nC1 = bits_to_normal(rnd_bits(one, kk0, kk1, i10 + 1u));
            float nD0 = bits_to_normal(rnd_bits(one, kk0, kk1, i11));
            float nD1 = bits_to_normal(rnd_bits(one, kk0, kk1, i11 + 1u));
            // --- MMA with split accumulator chains (depth 4 each) ---
            float D0a[4] = {0,0,0,0}, D0b[4] = {0,0,0,0};
            float D1a[4] = {0,0,0,0}, D1b[4] = {0,0,0,0};
            const uint32_t* xt0 = &smu[xtR + r0 * ROWP + xbase];
            const uint32_t* xt1 = &smu[xtR + r1 * ROWP + xbase];
#pragma unroll
            for (int j = 0; j < 4; j++) {
                uint4 va = *(const uint4*)(xt0 + 4 * j);
                uint4 vb = *(const uint4*)(xt1 + 4 * j);
                uint32_t a[4];
                a[0] = va.x; a[1] = vb.x; a[2] = va.y; a[3] = vb.y;
                mma_bf16(D0a, a, Bf[2 * j][0]);
                mma_bf16(D1a, a, Bf[2 * j][1]);
                a[0] = va.z; a[1] = vb.z; a[2] = va.w; a[3] = vb.w;
                mma_bf16(D0b, a, Bf[2 * j + 1][0]);
                mma_bf16(D1b, a, Bf[2 * j + 1][1]);
            }
            float D0[4], D1[4];
#pragma unroll
            for (int q = 0; q < 4; q++) {
                D0[q] = D0a[q] + D0b[q];
                D1[q] = D1a[q] + D1b[q];
            }
            // --- combine ---
            float2 xo00 = *(float2*)&sm[LG_XEX + r0 * PL_ROW + cA];
            float2 xo01 = *(float2*)&sm[LG_XEX + r0 * PL_ROW + cB];
            float2 xo10 = *(float2*)&sm[LG_XEX + r1 * PL_ROW + cA];
            float2 xo11 = *(float2*)&sm[LG_XEX + r1 * PL_ROW + cB];
            float2 c00 = *(float2*)&sm[LG_C + r0 * PL_ROW + cA];
            float2 c01 = *(float2*)&sm[LG_C + r0 * PL_ROW + cB];
            float2 c10 = *(float2*)&sm[LG_C + r1 * PL_ROW + cA];
            float2 c11 = *(float2*)&sm[LG_C + r1 * PL_ROW + cB];
            float2 n00, n01, n10, n11;
            n00.x = tanh_fast(fmaf(nA0, nscale, fmaf(D0[0], -0.1f, xo00.x + c00.x)));
            n00.y = tanh_fast(fmaf(nA1, nscale, fmaf(D0[1], -0.1f, xo00.y + c00.y)));
            n01.x = tanh_fast(fmaf(nB0, nscale, fmaf(D1[0], -0.1f, xo01.x + c01.x)));
            n01.y = tanh_fast(fmaf(nB1, nscale, fmaf(D1[1], -0.1f, xo01.y + c01.y)));
            n10.x = tanh_fast(fmaf(nC0, nscale, fmaf(D0[2], -0.1f, xo10.x + c10.x)));
            n10.y = tanh_fast(fmaf(nC1, nscale, fmaf(D0[3], -0.1f, xo10.y + c10.y)));
            n11.x = tanh_fast(fmaf(nD0, nscale, fmaf(D1[2], -0.1f, xo11.x + c11.x)));
            n11.y = tanh_fast(fmaf(nD1, nscale, fmaf(D1[3], -0.1f, xo11.y + c11.y)));
            *(float2*)&sm[LG_XEX + r0 * PL_ROW + cA] = n00;
            *(float2*)&sm[LG_XEX + r0 * PL_ROW + cB] = n01;
            *(float2*)&sm[LG_XEX + r1 * PL_ROW + cA] = n10;
            *(float2*)&sm[LG_XEX + r1 * PL_ROW + cB] = n11;
            if (!lastS) {
                smu[xtW + r0 * ROWP + xbase + sA] = pack_bf16(n00.y, n00.x);
                smu[xtW + r0 * ROWP + xbase + sB] = pack_bf16(n01.y, n01.x);
                smu[xtW + r1 * ROWP + xbase + sA] = pack_bf16(n10.y, n10.x);
                smu[xtW + r1 * ROWP + xbase + sB] = pack_bf16(n11.y, n11.x);
            }
        }
        __syncthreads();
    }

    // output copy, coalesced
    float4* o4 = (float4*)(out + (size_t)tb * 128);
    for (int idx = tid; idx < 2048; idx += NTHREADS) {
        int r = idx >> 5, q = idx & 31;
        o4[idx] = *(float4*)&sm[LG_XEX + r * PL_ROW + 4 * q];
    }
}

// ===========================================================================
// Launch
// ===========================================================================
extern "C" void kernel_launch(void* const* d_in, const int* in_sizes, int n_in,
                              void* d_out, int out_size)
{
    const float* x_input = (const float*)d_in[0];
    const float* W       = (const float*)d_in[1];
    const float* J       = (const float*)d_in[2];
    const float* h       = (const float*)d_in[3];
    float* out           = (float*)d_out;

    Keys keys;
    for (int s = 0; s < STEPS; s++) {
        uint32_t o0, o1;
        threefry_host(0u, 1u, 0u, (uint32_t)s, o0, o1);
        keys.k0[s] = o0;
        keys.k1[s] = o1;
    }
    keys.one = 1u;

    static bool attr_set = false;
    if (!attr_set) {
        cudaFuncSetAttribute(phase1_mma,
            cudaFuncAttributeMaxDynamicSharedMemorySize, P1_SMEM);
        cudaFuncSetAttribute(langevin_bf16,
            cudaFuncAttributeMaxDynamicSharedMemorySize, LG_SMEM);
        attr_set = true;
    }

    const int NT = B_ROWS / 64;
    zero_kernel<<<1, 1>>>();
    phase1_mma<<<NT, NTHREADS, P1_SMEM>>>(x_input, W);
    finalize_kernel<<<1, 1>>>();
    langevin_bf16<<<NT, NTHREADS, LG_SMEM>>>(x_input, J, h, out, keys);
}